// round 1
// baseline (speedup 1.0000x reference)
#include <cuda_runtime.h>
#include <math.h>

#define HID   2048
#define VOCAB 50257

// Scratch (no cudaMalloc allowed)
__device__ float        g_hnew[HID];
__device__ float        g_logits[VOCAB];
__device__ unsigned int g_max_u;
__device__ float        g_sum;

// ---------------------------------------------------------------------------
// Kernel 1: fused GRU cell. One block per hidden unit i.
// Computes rows i, H+i, 2H+i of both w_ih@x and w_hh@h, then the gate math.
// ---------------------------------------------------------------------------
__global__ void __launch_bounds__(256) gru_kernel(
    const int*   __restrict__ idx,
    const float* __restrict__ hidden,
    const float* __restrict__ embed,
    const float* __restrict__ w_ih,
    const float* __restrict__ w_hh,
    const float* __restrict__ b_ih,
    const float* __restrict__ b_hh,
    float*       __restrict__ hnew_out)   // may be null
{
    const int i   = blockIdx.x;
    const int tid = threadIdx.x;
    const int lane = tid & 31;
    const int warp = tid >> 5;

    // idx may be int32 or int64 (little-endian: low word is the value either way)
    const int token = idx[0];

    const float4* x4 = (const float4*)(embed + (size_t)token * HID);
    const float4* h4 = (const float4*)hidden;

    const float4* wi_r = (const float4*)(w_ih + (size_t)( i            ) * HID);
    const float4* wi_z = (const float4*)(w_ih + (size_t)( HID   + i    ) * HID);
    const float4* wi_n = (const float4*)(w_ih + (size_t)( 2*HID + i    ) * HID);
    const float4* wh_r = (const float4*)(w_hh + (size_t)( i            ) * HID);
    const float4* wh_z = (const float4*)(w_hh + (size_t)( HID   + i    ) * HID);
    const float4* wh_n = (const float4*)(w_hh + (size_t)( 2*HID + i    ) * HID);

    float acc[6] = {0.f, 0.f, 0.f, 0.f, 0.f, 0.f};

    #pragma unroll
    for (int it = 0; it < (HID/4)/256; it++) {
        const int k = tid + it * 256;
        const float4 xv = x4[k];
        const float4 hv = h4[k];
        float4 w;
        w = wi_r[k]; acc[0] += w.x*xv.x + w.y*xv.y + w.z*xv.z + w.w*xv.w;
        w = wi_z[k]; acc[1] += w.x*xv.x + w.y*xv.y + w.z*xv.z + w.w*xv.w;
        w = wi_n[k]; acc[2] += w.x*xv.x + w.y*xv.y + w.z*xv.z + w.w*xv.w;
        w = wh_r[k]; acc[3] += w.x*hv.x + w.y*hv.y + w.z*hv.z + w.w*hv.w;
        w = wh_z[k]; acc[4] += w.x*hv.x + w.y*hv.y + w.z*hv.z + w.w*hv.w;
        w = wh_n[k]; acc[5] += w.x*hv.x + w.y*hv.y + w.z*hv.z + w.w*hv.w;
    }

    // warp reduce all 6
    #pragma unroll
    for (int o = 16; o; o >>= 1) {
        #pragma unroll
        for (int j = 0; j < 6; j++)
            acc[j] += __shfl_xor_sync(0xffffffffu, acc[j], o);
    }

    __shared__ float s[8][6];
    if (lane == 0) {
        #pragma unroll
        for (int j = 0; j < 6; j++) s[warp][j] = acc[j];
    }
    __syncthreads();

    if (tid == 0) {
        float t[6];
        #pragma unroll
        for (int j = 0; j < 6; j++) {
            float v = s[0][j];
            #pragma unroll
            for (int w = 1; w < 8; w++) v += s[w][j];
            t[j] = v;
        }
        const float gir = t[0] + b_ih[i];
        const float giz = t[1] + b_ih[HID + i];
        const float gin = t[2] + b_ih[2*HID + i];
        const float ghr = t[3] + b_hh[i];
        const float ghz = t[4] + b_hh[HID + i];
        const float ghn = t[5] + b_hh[2*HID + i];

        const float r = 1.0f / (1.0f + expf(-(gir + ghr)));
        const float z = 1.0f / (1.0f + expf(-(giz + ghz)));
        const float n = tanhf(gin + r * ghn);
        const float hn = (1.0f - z) * n + z * hidden[i];

        g_hnew[i] = hn;
        if (hnew_out) hnew_out[i] = hn;
        if (i == 0) { g_max_u = 0u; g_sum = 0.0f; }
    }
}

// ---------------------------------------------------------------------------
// Kernel 2: logits = relu(w_out @ h_new + b_out). Warp-per-row, 8 rows/block.
// Tracks the global max via atomicMax on uint bits (valid: all values >= 0).
// ---------------------------------------------------------------------------
__global__ void __launch_bounds__(256) logits_kernel(
    const float* __restrict__ w_out,
    const float* __restrict__ b_out)
{
    const int lane = threadIdx.x & 31;
    const int warp = threadIdx.x >> 5;
    const int row  = blockIdx.x * 8 + warp;

    float l = 0.0f;
    if (row < VOCAB) {
        const float4* w4 = (const float4*)(w_out + (size_t)row * HID);
        const float4* h4 = (const float4*)g_hnew;
        float acc = 0.0f;
        #pragma unroll
        for (int j = 0; j < 16; j++) {
            const int k = lane + 32 * j;
            const float4 w = w4[k];
            const float4 h = h4[k];
            acc += w.x*h.x + w.y*h.y + w.z*h.z + w.w*h.w;
        }
        #pragma unroll
        for (int o = 16; o; o >>= 1)
            acc += __shfl_xor_sync(0xffffffffu, acc, o);
        l = fmaxf(acc + b_out[row], 0.0f);
        if (lane == 0) g_logits[row] = l;
    }

    __shared__ float smax[8];
    if (lane == 0) smax[warp] = l;
    __syncthreads();
    if (threadIdx.x == 0) {
        float m = smax[0];
        #pragma unroll
        for (int w = 1; w < 8; w++) m = fmaxf(m, smax[w]);
        atomicMax(&g_max_u, __float_as_uint(m));   // all values >= 0
    }
}

// ---------------------------------------------------------------------------
// Kernel 3: sum of exp(l - max)
// ---------------------------------------------------------------------------
__global__ void __launch_bounds__(256) sumexp_kernel()
{
    const float m = __uint_as_float(g_max_u);
    float s = 0.0f;
    for (int v = blockIdx.x * blockDim.x + threadIdx.x; v < VOCAB;
         v += gridDim.x * blockDim.x)
        s += expf(g_logits[v] - m);

    #pragma unroll
    for (int o = 16; o; o >>= 1)
        s += __shfl_xor_sync(0xffffffffu, s, o);

    __shared__ float sh[8];
    const int lane = threadIdx.x & 31;
    const int warp = threadIdx.x >> 5;
    if (lane == 0) sh[warp] = s;
    __syncthreads();
    if (threadIdx.x == 0) {
        float t = sh[0];
        #pragma unroll
        for (int w = 1; w < 8; w++) t += sh[w];
        atomicAdd(&g_sum, t);
    }
}

// ---------------------------------------------------------------------------
// Kernel 4: out[v] = l[v] - max - log(sum)
// ---------------------------------------------------------------------------
__global__ void __launch_bounds__(256) finalize_kernel(float* __restrict__ out)
{
    const int v = blockIdx.x * blockDim.x + threadIdx.x;
    if (v < VOCAB) {
        const float m = __uint_as_float(g_max_u);
        out[v] = g_logits[v] - m - logf(g_sum);
    }
}

// ---------------------------------------------------------------------------
extern "C" void kernel_launch(void* const* d_in, const int* in_sizes, int n_in,
                              void* d_out, int out_size)
{
    const int*   idx    = (const int*)  d_in[0];
    const float* hidden = (const float*)d_in[1];
    const float* embed  = (const float*)d_in[2];
    const float* w_ih   = (const float*)d_in[3];
    const float* w_hh   = (const float*)d_in[4];
    const float* b_ih   = (const float*)d_in[5];
    const float* b_hh   = (const float*)d_in[6];
    const float* w_out  = (const float*)d_in[7];
    const float* b_out  = (const float*)d_in[8];

    float* out = (float*)d_out;
    float* hnew_out = (out_size >= VOCAB + HID) ? (out + VOCAB) : nullptr;

    gru_kernel<<<HID, 256>>>(idx, hidden, embed, w_ih, w_hh, b_ih, b_hh, hnew_out);
    logits_kernel<<<(VOCAB + 7) / 8, 256>>>(w_out, b_out);
    sumexp_kernel<<<96, 256>>>();
    finalize_kernel<<<(VOCAB + 255) / 256, 256>>>(out);
}